// round 16
// baseline (speedup 1.0000x reference)
#include <cuda_runtime.h>
#include <cuda_fp16.h>
#include <cstdint>
#include <math.h>

#define S_DIM 256
#define I_DIM 256
#define CS    256
#define NH    8
#define HD    32
#define M_ROWS 65536
#define MBLOCKS 512
#define QSCALE 0.2550349f   /* log2(e) / sqrt(32) */

// ---------------------------------------------------------------------------
// Scratch (device globals). All intermediates plain fp16; weights fp16.
// ---------------------------------------------------------------------------
__device__ __align__(16) __half g_x   [M_ROWS * CS];
__device__ __align__(16) __half g_gv  [M_ROWS * CS];
__device__ __align__(16) __half g_q   [M_ROWS * CS];
__device__ __align__(16) __half g_k   [M_ROWS * CS];
__device__ __align__(16) __half g_v   [M_ROWS * CS];
__device__ __align__(16) __half g_g   [M_ROWS * CS];
__device__ __align__(16) __half g_wt  [5 * CS * CS];    // [w][k][n]

// ---------------------------------------------------------------------------
// Helpers
// ---------------------------------------------------------------------------
__device__ __forceinline__ uint32_t smem_u32(const void* p) {
    uint32_t a;
    asm("{ .reg .u64 t; cvta.to.shared.u64 t, %1; cvt.u32.u64 %0, t; }" : "=r"(a) : "l"(p));
    return a;
}
__device__ __forceinline__ void cpa16(uint32_t dst, const void* src) {
    asm volatile("{ .reg .u64 g; cvta.to.global.u64 g, %1;"
                 "  cp.async.cg.shared.global [%0], [g], 16; }"
                 :: "r"(dst), "l"(src) : "memory");
}
__device__ __forceinline__ void cpa_commit() {
    asm volatile("cp.async.commit_group;" ::: "memory");
}
template <int N>
__device__ __forceinline__ void cpa_wait() {
    asm volatile("cp.async.wait_group %0;" :: "n"(N) : "memory");
}
__device__ __forceinline__ void ldsm4(uint32_t* r, uint32_t addr) {
    asm volatile("ldmatrix.sync.aligned.m8n8.x4.shared.b16 {%0,%1,%2,%3}, [%4];"
                 : "=r"(r[0]), "=r"(r[1]), "=r"(r[2]), "=r"(r[3]) : "r"(addr));
}
__device__ __forceinline__ void ldsm4t(uint32_t* r, uint32_t addr) {
    asm volatile("ldmatrix.sync.aligned.m8n8.x4.trans.shared.b16 {%0,%1,%2,%3}, [%4];"
                 : "=r"(r[0]), "=r"(r[1]), "=r"(r[2]), "=r"(r[3]) : "r"(addr));
}
__device__ __forceinline__ void mma_f16(float* c, const uint32_t* a, const uint32_t* b) {
    asm volatile("mma.sync.aligned.m16n8k16.row.col.f32.f16.f16.f32 "
                 "{%0,%1,%2,%3}, {%4,%5,%6,%7}, {%8,%9}, {%0,%1,%2,%3};"
                 : "+f"(c[0]), "+f"(c[1]), "+f"(c[2]), "+f"(c[3])
                 : "r"(a[0]), "r"(a[1]), "r"(a[2]), "r"(a[3]), "r"(b[0]), "r"(b[1]));
}
__device__ __forceinline__ uint32_t h2pack(float a, float b) {
    __half2 t = __floats2half2_rn(a, b);
    return *reinterpret_cast<uint32_t*>(&t);
}
__device__ __forceinline__ float ex2f(float x) {
    float r;
    asm("ex2.approx.f32 %0, %1;" : "=f"(r) : "f"(x));
    return r;
}

// ---------------------------------------------------------------------------
// Kernel 1: fused LayerNorm (blocks 0..8191) + weight fp16 convert (rest)
// ---------------------------------------------------------------------------
#define LN_BLOCKS (M_ROWS / 8)
#define WP_BLOCKS (5 * 65536 / 256)

__global__ void __launch_bounds__(256) prep_kernel(const float* __restrict__ msa,
                                                   const float* __restrict__ gamma,
                                                   const float* __restrict__ beta,
                                                   const float* __restrict__ Wq,
                                                   const float* __restrict__ Wk,
                                                   const float* __restrict__ Wv,
                                                   const float* __restrict__ Wg,
                                                   const float* __restrict__ Wo)
{
    if (blockIdx.x >= LN_BLOCKS) {
        const int idx = (blockIdx.x - LN_BLOCKS) * 256 + threadIdx.x;
        const int w = idx >> 16;
        const int e = idx & 65535;
        const float* W = (w == 0) ? Wq : (w == 1) ? Wk : (w == 2) ? Wv : (w == 3) ? Wg : Wo;
        g_wt[idx] = __float2half_rn(W[e]);
        return;
    }
    const int lane = threadIdx.x & 31;
    const int row = blockIdx.x * 8 + (threadIdx.x >> 5);
    const float* rp = msa + (size_t)row * CS + lane * 8;

    const float4 v0 = *(const float4*)rp;
    const float4 v1 = *(const float4*)(rp + 4);
    float s1 = v0.x + v0.y + v0.z + v0.w + v1.x + v1.y + v1.z + v1.w;
    float s2 = v0.x * v0.x + v0.y * v0.y + v0.z * v0.z + v0.w * v0.w
             + v1.x * v1.x + v1.y * v1.y + v1.z * v1.z + v1.w * v1.w;
    #pragma unroll
    for (int o = 16; o > 0; o >>= 1) {
        s1 += __shfl_xor_sync(0xFFFFFFFFu, s1, o);
        s2 += __shfl_xor_sync(0xFFFFFFFFu, s2, o);
    }
    const float mu = s1 * (1.0f / CS);
    const float var = s2 * (1.0f / CS) - mu * mu;
    const float rstd = rsqrtf(var + 1e-5f);

    const float4 gm0 = *(const float4*)(gamma + lane * 8);
    const float4 gm1 = *(const float4*)(gamma + lane * 8 + 4);
    const float4 bt0 = *(const float4*)(beta + lane * 8);
    const float4 bt1 = *(const float4*)(beta + lane * 8 + 4);

    uint4 out;
    out.x = h2pack((v0.x - mu) * rstd * gm0.x + bt0.x, (v0.y - mu) * rstd * gm0.y + bt0.y);
    out.y = h2pack((v0.z - mu) * rstd * gm0.z + bt0.z, (v0.w - mu) * rstd * gm0.w + bt0.w);
    out.z = h2pack((v1.x - mu) * rstd * gm1.x + bt1.x, (v1.y - mu) * rstd * gm1.y + bt1.y);
    out.w = h2pack((v1.z - mu) * rstd * gm1.z + bt1.z, (v1.w - mu) * rstd * gm1.w + bt1.w);
    *(uint4*)(g_x + (size_t)row * CS + lane * 8) = out;
}

// ---------------------------------------------------------------------------
// Projection GEMM, A-resident: CTA = (mblk, nblk). A tile (128x256 fp16) is
// loaded to smem ONCE; the 4 weights' B tiles stream through a 4-buffer ring
// with a global stage counter g = w*8 + ks (seamless cross-w prefetch).
// L2 read traffic: A x1 instead of x4. 256 thr / 8 warps, warp tile 64x32,
// BK=32, 2 CTAs/SM. MMA order per GEMM identical to split kernels.
// ---------------------------------------------------------------------------
#define PA_ROW 528u
#define PA_SZ  67584u
#define PB_STG 8704u
#define PROJ_SMEM (67584 + 4 * 8704)

__device__ __forceinline__ void proj_load_b(uint32_t st, int g, int tid, int nblk)
{
    const int w = g >> 3, ks = g & 7;
    const __half* bH = g_wt + (size_t)w * 65536;
    #pragma unroll
    for (int j = 0; j < 2; j++) {
        const int u = tid + 256 * j;
        const int row = u >> 4, col = u & 15;
        cpa16(st + (uint32_t)(row * 272 + col * 16),
              bH + (size_t)(ks * 32 + row) * CS + nblk * 128 + col * 8);
    }
}

__global__ void __launch_bounds__(256, 2) gemm_proj(const float* __restrict__ bg)
{
    extern __shared__ unsigned char smem[];
    const uint32_t sb = smem_u32(smem);
    const int tid = threadIdx.x;
    const int lane = tid & 31;
    const int wid = tid >> 5;
    const int wm = wid >> 2;
    const int wn = wid & 3;
    const int mblk = blockIdx.x;
    const int nblk = blockIdx.y;

    // ---- load full A tile (128 rows x 512B, 528B padded rows) ----
    #pragma unroll
    for (int j = 0; j < 16; j++) {
        const int u = tid + 256 * j;
        const int row = u >> 5, col = u & 31;
        cpa16(sb + (uint32_t)row * PA_ROW + (uint32_t)(col * 16),
              g_x + (size_t)(mblk * 128 + row) * CS + col * 8);
    }
    cpa_commit();

    // ---- prime B ring with stages 0..2 ----
    proj_load_b(sb + PA_SZ,              0, tid, nblk); cpa_commit();
    proj_load_b(sb + PA_SZ + PB_STG,     1, tid, nblk); cpa_commit();
    proj_load_b(sb + PA_SZ + 2 * PB_STG, 2, tid, nblk); cpa_commit();

    const uint32_t aRowSel = (uint32_t)((wm * 64 + (lane & 15)) * PA_ROW + (lane >> 4) * 16);
    const uint32_t bColSel = (uint32_t)((wn * 32 + (lane >> 4) * 8) * 2);

    for (int w = 0; w < 4; w++) {
        float acc[4][4][4];
        #pragma unroll
        for (int i = 0; i < 4; i++)
            #pragma unroll
            for (int j = 0; j < 4; j++)
                #pragma unroll
                for (int q = 0; q < 4; q++) acc[i][j][q] = 0.f;

        for (int ks = 0; ks < 8; ks++) {
            const int g = w * 8 + ks;
            if (g <= 29) cpa_wait<2>(); else if (g == 30) cpa_wait<1>(); else cpa_wait<0>();
            __syncthreads();
            if (g + 3 < 32) {
                proj_load_b(sb + PA_SZ + (uint32_t)((g + 3) & 3) * PB_STG, g + 3, tid, nblk);
                cpa_commit();
            }
            const uint32_t bst = sb + PA_SZ + (uint32_t)(g & 3) * PB_STG;

            #pragma unroll
            for (int kh = 0; kh < 2; kh++) {
                uint32_t Af[4][4], Bh[4][2];
                const uint32_t kOff = (uint32_t)(ks * 64 + kh * 32);
                #pragma unroll
                for (int mf = 0; mf < 4; mf++)
                    ldsm4(Af[mf], sb + aRowSel + (uint32_t)(mf * 16) * PA_ROW + kOff);
                const uint32_t bBase = bst + (uint32_t)((kh * 16 + (lane & 15)) * 272) + bColSel;
                #pragma unroll
                for (int gg = 0; gg < 2; gg++) {
                    uint32_t r[4];
                    ldsm4t(r, bBase + (uint32_t)(gg * 32));
                    Bh[2 * gg][0] = r[0]; Bh[2 * gg][1] = r[1];
                    Bh[2 * gg + 1][0] = r[2]; Bh[2 * gg + 1][1] = r[3];
                }
                #pragma unroll
                for (int mf = 0; mf < 4; mf++)
                    #pragma unroll
                    for (int nf = 0; nf < 4; nf++)
                        mma_f16(acc[mf][nf], Af[mf], Bh[nf]);
            }
        }

        // ---- epilogue for this weight (regs + global only; no smem) ----
        __half* Ch = (w == 0) ? g_q : (w == 1) ? g_k : (w == 2) ? g_v : g_g;
        const int r0 = mblk * 128 + wm * 64 + (lane >> 2);
        const int c0 = nblk * 128 + wn * 32 + (lane & 3) * 2;
        #pragma unroll
        for (int mf = 0; mf < 4; mf++) {
            #pragma unroll
            for (int nf = 0; nf < 4; nf++) {
                const int n = c0 + nf * 8;
                const int m = r0 + mf * 16;
                float v0 = acc[mf][nf][0], v1 = acc[mf][nf][1];
                float v2 = acc[mf][nf][2], v3 = acc[mf][nf][3];
                if (w == 0) {
                    v0 *= QSCALE; v1 *= QSCALE; v2 *= QSCALE; v3 *= QSCALE;
                } else if (w == 3) {
                    const float b0 = __ldg(bg + n), b1 = __ldg(bg + n + 1);
                    v0 = 1.f / (1.f + __expf(-(v0 + b0)));
                    v1 = 1.f / (1.f + __expf(-(v1 + b1)));
                    v2 = 1.f / (1.f + __expf(-(v2 + b0)));
                    v3 = 1.f / (1.f + __expf(-(v3 + b1)));
                }
                *(uint32_t*)(Ch + (size_t)m * CS + n)       = h2pack(v0, v1);
                *(uint32_t*)(Ch + (size_t)(m + 8) * CS + n) = h2pack(v2, v3);
            }
        }
    }
}

// ---------------------------------------------------------------------------
// Output GEMM (round-15 proven 4-stage body): out = gv @ Wo + bo (fp32)
// ---------------------------------------------------------------------------
#define GB_OFF  10240u
#define GSTAGE  18944u
#define GEMM_SMEM (4 * 18944)

__device__ __forceinline__ void gemm_load_stage(uint32_t st, int ks, int tid,
                                                int mblk, int nblk,
                                                const __half* __restrict__ aP,
                                                const __half* __restrict__ bH)
{
    #pragma unroll
    for (int j = 0; j < 2; j++) {
        const int u = tid + 256 * j;
        const int ar = u >> 2, ac = u & 3;
        cpa16(st + (uint32_t)(ar * 80 + ac * 16),
              aP + (size_t)(mblk * 128 + ar) * CS + ks * 32 + ac * 8);
    }
    #pragma unroll
    for (int j = 0; j < 2; j++) {
        const int u = tid + 256 * j;
        const int row = u >> 4, col = u & 15;
        cpa16(st + GB_OFF + (uint32_t)(row * 272 + col * 16),
              bH + (size_t)(ks * 32 + row) * CS + nblk * 128 + col * 8);
    }
}

__global__ void __launch_bounds__(256, 2) gemm_outp(const float* __restrict__ bo,
                                                    float* __restrict__ out)
{
    extern __shared__ unsigned char smem[];
    const uint32_t sb = smem_u32(smem);
    const int tid = threadIdx.x;
    const int lane = tid & 31;
    const int wid = tid >> 5;
    const int wm = wid >> 2;
    const int wn = wid & 3;
    const int mblk = blockIdx.x;
    const int nblk = blockIdx.y;
    const __half* bH = g_wt + (size_t)4 * 65536;

    float acc[4][4][4];
    #pragma unroll
    for (int i = 0; i < 4; i++)
        #pragma unroll
        for (int j = 0; j < 4; j++)
            #pragma unroll
            for (int q = 0; q < 4; q++) acc[i][j][q] = 0.f;

    gemm_load_stage(sb,              0, tid, mblk, nblk, g_gv, bH);
    cpa_commit();
    gemm_load_stage(sb + GSTAGE,     1, tid, mblk, nblk, g_gv, bH);
    cpa_commit();
    gemm_load_stage(sb + 2 * GSTAGE, 2, tid, mblk, nblk, g_gv, bH);
    cpa_commit();

    const uint32_t aRowSel = (uint32_t)((wm * 64 + (lane & 15)) * 80 + (lane >> 4) * 16);
    const uint32_t bColSel = (uint32_t)((wn * 32 + (lane >> 4) * 8) * 2);

    for (int ks = 0; ks < 8; ks++) {
        if (ks < 6) cpa_wait<2>(); else if (ks == 6) cpa_wait<1>(); else cpa_wait<0>();
        __syncthreads();
        if (ks + 3 < 8) {
            gemm_load_stage(sb + (uint32_t)((ks + 3) & 3) * GSTAGE, ks + 3, tid,
                            mblk, nblk, g_gv, bH);
            cpa_commit();
        }
        const uint32_t st = sb + (uint32_t)(ks & 3) * GSTAGE;

        #pragma unroll
        for (int kh = 0; kh < 2; kh++) {
            uint32_t Af[4][4], Bh[4][2];
            #pragma unroll
            for (int mf = 0; mf < 4; mf++)
                ldsm4(Af[mf], st + aRowSel + (uint32_t)(mf * 16 * 80 + kh * 32));
            const uint32_t bBase = st + GB_OFF +
                (uint32_t)((kh * 16 + (lane & 15)) * 272) + bColSel;
            #pragma unroll
            for (int g = 0; g < 2; g++) {
                uint32_t r[4];
                ldsm4t(r, bBase + (uint32_t)(g * 32));
                Bh[2 * g][0] = r[0]; Bh[2 * g][1] = r[1];
                Bh[2 * g + 1][0] = r[2]; Bh[2 * g + 1][1] = r[3];
            }
            #pragma unroll
            for (int mf = 0; mf < 4; mf++)
                #pragma unroll
                for (int nf = 0; nf < 4; nf++)
                    mma_f16(acc[mf][nf], Af[mf], Bh[nf]);
        }
    }

    const int r0 = mblk * 128 + wm * 64 + (lane >> 2);
    const int c0 = nblk * 128 + wn * 32 + (lane & 3) * 2;
    #pragma unroll
    for (int mf = 0; mf < 4; mf++) {
        #pragma unroll
        for (int nf = 0; nf < 4; nf++) {
            const int n = c0 + nf * 8;
            const int m = r0 + mf * 16;
            const float b0 = __ldg(bo + n), b1 = __ldg(bo + n + 1);
            *(float2*)(out + (size_t)m * CS + n) =
                make_float2(acc[mf][nf][0] + b0, acc[mf][nf][1] + b1);
            *(float2*)(out + (size_t)(m + 8) * CS + n) =
                make_float2(acc[mf][nf][2] + b0, acc[mf][nf][3] + b1);
        }
    }
}

// ---------------------------------------------------------------------------
// Kernel 3: tensor-core column attention (round-13/15 proven config).
// Grid (i, h). Block = one (i, h). 256 thr = 8 warps, 32 queries/warp,
// 2 CTAs/SM. lsum via ones-MMA. Stage = K, V @ 64 rows x 80B.
// ---------------------------------------------------------------------------
#define AQ_SZ   20480u
#define AST_OFF 20480u
#define AST_SZ  10240u
#define ATTN_SMEM (20480 + 3 * 10240)

__device__ __forceinline__ void load_kv_stage(uint32_t stbase, int i, int h, int t0, int tid)
{
    #pragma unroll
    for (int j = 0; j < 2; j++) {
        const int u = tid + 256 * j;
        const int arr = u >> 8;
        const int rem = u & 255;
        const int row = rem >> 2;
        const int c = rem & 3;
        const __half* base = (arr == 0) ? g_k : g_v;
        const __half* src = base + ((size_t)(t0 + row) * I_DIM + i) * CS + h * HD + c * 8;
        cpa16(stbase + (uint32_t)(arr * 5120 + row * 80 + c * 16), src);
    }
}

__global__ void __launch_bounds__(256, 2) attn_kernel()
{
    extern __shared__ unsigned char sm[];
    const uint32_t sb = smem_u32(sm);
    const int i = blockIdx.x;
    const int h = blockIdx.y;
    const int tid = threadIdx.x;
    const int lane = tid & 31;
    const int wq = tid >> 5;

    #pragma unroll
    for (int j = 0; j < 4; j++) {
        const int u = tid + 256 * j;
        const int row = u >> 2, c = u & 3;
        cpa16(sb + (uint32_t)(row * 80 + c * 16),
              g_q + ((size_t)row * I_DIM + i) * CS + h * HD + c * 8);
    }
    cpa_commit();
    load_kv_stage(sb + AST_OFF, i, h, 0, tid);
    cpa_commit();
    load_kv_stage(sb + AST_OFF + AST_SZ, i, h, 64, tid);
    cpa_commit();

    cpa_wait<2>();
    __syncthreads();

    uint32_t qf[2][2][4];
    #pragma unroll
    for (int mf = 0; mf < 2; mf++) {
        const uint32_t qrow = (uint32_t)((wq * 32 + mf * 16 + (lane & 15)) * 80
                                         + (lane >> 4) * 16);
        ldsm4(qf[mf][0], sb + qrow);
        ldsm4(qf[mf][1], sb + qrow + 32u);
    }

    float o[2][4][4];
    #pragma unroll
    for (int mf = 0; mf < 2; mf++)
        #pragma unroll
        for (int nf = 0; nf < 4; nf++)
            #pragma unroll
            for (int q = 0; q < 4; q++) o[mf][nf][q] = 0.f;
    float lacc[2][4];
    #pragma unroll
    for (int mf = 0; mf < 2; mf++)
        #pragma unroll
        for (int q = 0; q < 4; q++) lacc[mf][q] = 0.f;

    const uint32_t ones[2] = {0x3C003C00u, 0x3C003C00u};

    const uint32_t kaddr = (uint32_t)((((lane >> 4) * 8) + (lane & 7)) * 80 + ((lane >> 3) & 1) * 16);
    const uint32_t vaddr = (uint32_t)(((((lane >> 3) & 1) * 8) + (lane & 7)) * 80 + (lane >> 4) * 16);

    for (int kt = 0; kt < 4; kt++) {
        if (kt < 3) cpa_wait<1>(); else cpa_wait<0>();
        __syncthreads();
        if (kt + 2 < 4) {
            load_kv_stage(sb + AST_OFF + (uint32_t)((kt + 2) % 3) * AST_SZ, i, h, (kt + 2) * 64, tid);
            cpa_commit();
        }
        const uint32_t st = sb + AST_OFF + (uint32_t)(kt % 3) * AST_SZ;

        #pragma unroll
        for (int ch = 0; ch < 4; ch++) {
            const uint32_t roff = (uint32_t)(ch * 16 * 80);

            float s[2][2][4];
            #pragma unroll
            for (int nt = 0; nt < 2; nt++)
                #pragma unroll
                for (int mf = 0; mf < 2; mf++)
                    #pragma unroll
                    for (int q = 0; q < 4; q++) s[nt][mf][q] = 0.f;

            #pragma unroll
            for (int ks = 0; ks < 2; ks++) {
                uint32_t bh[2][2], r[4];
                ldsm4(r, st + roff + kaddr + (uint32_t)(ks * 32));
                bh[0][0] = r[0]; bh[0][1] = r[1]; bh[1][0] = r[2]; bh[1][1] = r[3];
                #pragma unroll
                for (int nt = 0; nt < 2; nt++)
                    #pragma unroll
                    for (int mf = 0; mf < 2; mf++)
                        mma_f16(s[nt][mf], qf[mf][ks], bh[nt]);
            }

            uint32_t vhf[4][2];
            #pragma unroll
            for (int np2 = 0; np2 < 2; np2++) {
                uint32_t r[4];
                ldsm4t(r, st + 5120u + roff + vaddr + (uint32_t)(np2 * 32));
                vhf[2 * np2][0] = r[0]; vhf[2 * np2][1] = r[1];
                vhf[2 * np2 + 1][0] = r[2]; vhf[2 * np2 + 1][1] = r[3];
            }

            #pragma unroll
            for (int mf = 0; mf < 2; mf++) {
                float* sa = s[0][mf];
                float* sc = s[1][mf];
                sa[0] = ex2f(sa[0]); sa[1] = ex2f(sa[1]);
                sa[2] = ex2f(sa[2]); sa[3] = ex2f(sa[3]);
                sc[0] = ex2f(sc[0]); sc[1] = ex2f(sc[1]);
                sc[2] = ex2f(sc[2]); sc[3] = ex2f(sc[3]);
                uint32_t pA[4];
                pA[0] = h2pack(sa[0], sa[1]);
                pA[1] = h2pack(sa[2], sa[3]);
                pA[2] = h2pack(sc[0], sc[1]);
                pA[3] = h2pack(sc[2], sc[3]);
                mma_f16(lacc[mf], pA, ones);
                #pragma unroll
                for (int nf = 0; nf < 4; nf++)
                    mma_f16(o[mf][nf], pA, vhf[nf]);
            }
        }
    }

    #pragma unroll
    for (int mf = 0; mf < 2; mf++) {
        const float inv0 = 1.f / lacc[mf][0];
        const float inv1 = 1.f / lacc[mf][2];

        const int row = wq * 32 + mf * 16 + (lane >> 2);
        const size_t M0 = ((size_t)row * I_DIM + i) * CS + h * HD;
        const size_t M1 = ((size_t)(row + 8) * I_DIM + i) * CS + h * HD;
        #pragma unroll
        for (int nf = 0; nf < 4; nf++) {
            const int col = nf * 8 + (lane & 3) * 2;
            const float2 g0 = __half22float2(*(const __half2*)(g_g + M0 + col));
            const float2 g1 = __half22float2(*(const __half2*)(g_g + M1 + col));
            *(uint32_t*)(g_gv + M0 + col) =
                h2pack(o[mf][nf][0] * inv0 * g0.x, o[mf][nf][1] * inv0 * g0.y);
            *(uint32_t*)(g_gv + M1 + col) =
                h2pack(o[mf][nf][2] * inv1 * g1.x, o[mf][nf][3] * inv1 * g1.y);
        }
    }
}

// ---------------------------------------------------------------------------
// Launch
// ---------------------------------------------------------------------------
extern "C" void kernel_launch(void* const* d_in, const int* in_sizes, int n_in,
                              void* d_out, int out_size)
{
    const float* msa   = (const float*)d_in[0];
    const float* gamma = (const float*)d_in[1];
    const float* beta  = (const float*)d_in[2];
    const float* Wq    = (const float*)d_in[3];
    const float* Wk    = (const float*)d_in[4];
    const float* Wv    = (const float*)d_in[5];
    const float* Wg    = (const float*)d_in[6];
    const float* bg    = (const float*)d_in[7];
    const float* Wo    = (const float*)d_in[8];
    const float* bo    = (const float*)d_in[9];
    float* out = (float*)d_out;

    cudaFuncSetAttribute(gemm_proj, cudaFuncAttributeMaxDynamicSharedMemorySize, PROJ_SMEM);
    cudaFuncSetAttribute(gemm_outp, cudaFuncAttributeMaxDynamicSharedMemorySize, GEMM_SMEM);
    cudaFuncSetAttribute(attn_kernel, cudaFuncAttributeMaxDynamicSharedMemorySize, ATTN_SMEM);

    prep_kernel<<<LN_BLOCKS + WP_BLOCKS, 256>>>(msa, gamma, beta, Wq, Wk, Wv, Wg, Wo);

    gemm_proj<<<dim3(MBLOCKS, 2), 256, PROJ_SMEM>>>(bg);

    attn_kernel<<<dim3(I_DIM, NH), 256, ATTN_SMEM>>>();

    gemm_outp<<<dim3(MBLOCKS, 2), 256, GEMM_SMEM>>>(bo, out);
}

// round 17
// speedup vs baseline: 1.0137x; 1.0137x over previous
#include <cuda_runtime.h>
#include <cuda_fp16.h>
#include <cstdint>
#include <math.h>

#define S_DIM 256
#define I_DIM 256
#define CS    256
#define NH    8
#define HD    32
#define M_ROWS 65536
#define MBLOCKS 512
#define QSCALE 0.2550349f   /* log2(e) / sqrt(32) */

// ---------------------------------------------------------------------------
// Scratch (device globals). All intermediates plain fp16; weights fp16.
// ---------------------------------------------------------------------------
__device__ __align__(16) __half g_x   [M_ROWS * CS];
__device__ __align__(16) __half g_gv  [M_ROWS * CS];
__device__ __align__(16) __half g_q   [M_ROWS * CS];
__device__ __align__(16) __half g_k   [M_ROWS * CS];
__device__ __align__(16) __half g_v   [M_ROWS * CS];
__device__ __align__(16) __half g_g   [M_ROWS * CS];
__device__ __align__(16) __half g_wt  [5 * CS * CS];    // [w][k][n]

// ---------------------------------------------------------------------------
// Helpers
// ---------------------------------------------------------------------------
__device__ __forceinline__ uint32_t smem_u32(const void* p) {
    uint32_t a;
    asm("{ .reg .u64 t; cvta.to.shared.u64 t, %1; cvt.u32.u64 %0, t; }" : "=r"(a) : "l"(p));
    return a;
}
__device__ __forceinline__ void cpa16(uint32_t dst, const void* src) {
    asm volatile("{ .reg .u64 g; cvta.to.global.u64 g, %1;"
                 "  cp.async.cg.shared.global [%0], [g], 16; }"
                 :: "r"(dst), "l"(src) : "memory");
}
__device__ __forceinline__ void cpa_commit() {
    asm volatile("cp.async.commit_group;" ::: "memory");
}
template <int N>
__device__ __forceinline__ void cpa_wait() {
    asm volatile("cp.async.wait_group %0;" :: "n"(N) : "memory");
}
__device__ __forceinline__ void ldsm4(uint32_t* r, uint32_t addr) {
    asm volatile("ldmatrix.sync.aligned.m8n8.x4.shared.b16 {%0,%1,%2,%3}, [%4];"
                 : "=r"(r[0]), "=r"(r[1]), "=r"(r[2]), "=r"(r[3]) : "r"(addr));
}
__device__ __forceinline__ void ldsm4t(uint32_t* r, uint32_t addr) {
    asm volatile("ldmatrix.sync.aligned.m8n8.x4.trans.shared.b16 {%0,%1,%2,%3}, [%4];"
                 : "=r"(r[0]), "=r"(r[1]), "=r"(r[2]), "=r"(r[3]) : "r"(addr));
}
__device__ __forceinline__ void mma_f16(float* c, const uint32_t* a, const uint32_t* b) {
    asm volatile("mma.sync.aligned.m16n8k16.row.col.f32.f16.f16.f32 "
                 "{%0,%1,%2,%3}, {%4,%5,%6,%7}, {%8,%9}, {%0,%1,%2,%3};"
                 : "+f"(c[0]), "+f"(c[1]), "+f"(c[2]), "+f"(c[3])
                 : "r"(a[0]), "r"(a[1]), "r"(a[2]), "r"(a[3]), "r"(b[0]), "r"(b[1]));
}
__device__ __forceinline__ uint32_t h2pack(float a, float b) {
    __half2 t = __floats2half2_rn(a, b);
    return *reinterpret_cast<uint32_t*>(&t);
}
__device__ __forceinline__ float ex2f(float x) {
    float r;
    asm("ex2.approx.f32 %0, %1;" : "=f"(r) : "f"(x));
    return r;
}

// ---------------------------------------------------------------------------
// Kernel 1: fused LayerNorm (blocks 0..8191) + weight fp16 convert (rest)
// ---------------------------------------------------------------------------
#define LN_BLOCKS (M_ROWS / 8)
#define WP_BLOCKS (5 * 65536 / 256)

__global__ void __launch_bounds__(256) prep_kernel(const float* __restrict__ msa,
                                                   const float* __restrict__ gamma,
                                                   const float* __restrict__ beta,
                                                   const float* __restrict__ Wq,
                                                   const float* __restrict__ Wk,
                                                   const float* __restrict__ Wv,
                                                   const float* __restrict__ Wg,
                                                   const float* __restrict__ Wo)
{
    if (blockIdx.x >= LN_BLOCKS) {
        const int idx = (blockIdx.x - LN_BLOCKS) * 256 + threadIdx.x;
        const int w = idx >> 16;
        const int e = idx & 65535;
        const float* W = (w == 0) ? Wq : (w == 1) ? Wk : (w == 2) ? Wv : (w == 3) ? Wg : Wo;
        g_wt[idx] = __float2half_rn(W[e]);
        return;
    }
    const int lane = threadIdx.x & 31;
    const int row = blockIdx.x * 8 + (threadIdx.x >> 5);
    const float* rp = msa + (size_t)row * CS + lane * 8;

    const float4 v0 = *(const float4*)rp;
    const float4 v1 = *(const float4*)(rp + 4);
    float s1 = v0.x + v0.y + v0.z + v0.w + v1.x + v1.y + v1.z + v1.w;
    float s2 = v0.x * v0.x + v0.y * v0.y + v0.z * v0.z + v0.w * v0.w
             + v1.x * v1.x + v1.y * v1.y + v1.z * v1.z + v1.w * v1.w;
    #pragma unroll
    for (int o = 16; o > 0; o >>= 1) {
        s1 += __shfl_xor_sync(0xFFFFFFFFu, s1, o);
        s2 += __shfl_xor_sync(0xFFFFFFFFu, s2, o);
    }
    const float mu = s1 * (1.0f / CS);
    const float var = s2 * (1.0f / CS) - mu * mu;
    const float rstd = rsqrtf(var + 1e-5f);

    const float4 gm0 = *(const float4*)(gamma + lane * 8);
    const float4 gm1 = *(const float4*)(gamma + lane * 8 + 4);
    const float4 bt0 = *(const float4*)(beta + lane * 8);
    const float4 bt1 = *(const float4*)(beta + lane * 8 + 4);

    uint4 out;
    out.x = h2pack((v0.x - mu) * rstd * gm0.x + bt0.x, (v0.y - mu) * rstd * gm0.y + bt0.y);
    out.y = h2pack((v0.z - mu) * rstd * gm0.z + bt0.z, (v0.w - mu) * rstd * gm0.w + bt0.w);
    out.z = h2pack((v1.x - mu) * rstd * gm1.x + bt1.x, (v1.y - mu) * rstd * gm1.y + bt1.y);
    out.w = h2pack((v1.z - mu) * rstd * gm1.z + bt1.z, (v1.w - mu) * rstd * gm1.w + bt1.w);
    *(uint4*)(g_x + (size_t)row * CS + lane * 8) = out;
}

// ---------------------------------------------------------------------------
// HMMA GEMM body (R15 proven): C[128,128] = A[128,256] @ W[256,128-slice].
// 256 threads / 8 warps (2m x 4n), warp tile 64x32, BK=32 (8 iters),
// 4-stage cp.async, 2 CTAs/SM.
// mode: 0 = QSCALE + fp16, 4 = plain fp16, 2 = sigmoid(x+bias) fp16,
//       3 = x+bias fp32
// ---------------------------------------------------------------------------
#define GB_OFF  10240u
#define GSTAGE  18944u
#define GEMM_SMEM (4 * 18944)

__device__ __forceinline__ void gemm_load_stage(uint32_t st, int ks, int tid,
                                                int mblk, int nblk,
                                                const __half* __restrict__ aP,
                                                const __half* __restrict__ bH)
{
    #pragma unroll
    for (int j = 0; j < 2; j++) {
        const int u = tid + 256 * j;
        const int ar = u >> 2, ac = u & 3;
        cpa16(st + (uint32_t)(ar * 80 + ac * 16),
              aP + (size_t)(mblk * 128 + ar) * CS + ks * 32 + ac * 8);
    }
    #pragma unroll
    for (int j = 0; j < 2; j++) {
        const int u = tid + 256 * j;
        const int row = u >> 4, col = u & 15;
        cpa16(st + GB_OFF + (uint32_t)(row * 272 + col * 16),
              bH + (size_t)(ks * 32 + row) * CS + nblk * 128 + col * 8);
    }
}

__device__ __forceinline__ void gemm_body(const __half* __restrict__ aP,
                                          const __half* __restrict__ bH,
                                          const float* __restrict__ bias,
                                          float* __restrict__ Cf,
                                          __half* __restrict__ Ch,
                                          int mode, int mblk, int nblk)
{
    extern __shared__ unsigned char smem[];
    const uint32_t sb = smem_u32(smem);
    const int tid = threadIdx.x;
    const int lane = tid & 31;
    const int wid = tid >> 5;
    const int wm = wid >> 2;
    const int wn = wid & 3;

    float acc[4][4][4];
    #pragma unroll
    for (int i = 0; i < 4; i++)
        #pragma unroll
        for (int j = 0; j < 4; j++)
            #pragma unroll
            for (int q = 0; q < 4; q++) acc[i][j][q] = 0.f;

    gemm_load_stage(sb,              0, tid, mblk, nblk, aP, bH);
    cpa_commit();
    gemm_load_stage(sb + GSTAGE,     1, tid, mblk, nblk, aP, bH);
    cpa_commit();
    gemm_load_stage(sb + 2 * GSTAGE, 2, tid, mblk, nblk, aP, bH);
    cpa_commit();

    const uint32_t aRowSel = (uint32_t)((wm * 64 + (lane & 15)) * 80 + (lane >> 4) * 16);
    const uint32_t bColSel = (uint32_t)((wn * 32 + (lane >> 4) * 8) * 2);

    for (int ks = 0; ks < 8; ks++) {
        if (ks < 6) cpa_wait<2>(); else if (ks == 6) cpa_wait<1>(); else cpa_wait<0>();
        __syncthreads();
        if (ks + 3 < 8) {
            gemm_load_stage(sb + (uint32_t)((ks + 3) & 3) * GSTAGE, ks + 3, tid,
                            mblk, nblk, aP, bH);
            cpa_commit();
        }
        const uint32_t st = sb + (uint32_t)(ks & 3) * GSTAGE;

        #pragma unroll
        for (int kh = 0; kh < 2; kh++) {
            uint32_t Af[4][4], Bh[4][2];
            #pragma unroll
            for (int mf = 0; mf < 4; mf++)
                ldsm4(Af[mf], st + aRowSel + (uint32_t)(mf * 16 * 80 + kh * 32));
            const uint32_t bBase = st + GB_OFF +
                (uint32_t)((kh * 16 + (lane & 15)) * 272) + bColSel;
            #pragma unroll
            for (int g = 0; g < 2; g++) {
                uint32_t r[4];
                ldsm4t(r, bBase + (uint32_t)(g * 32));
                Bh[2 * g][0] = r[0]; Bh[2 * g][1] = r[1];
                Bh[2 * g + 1][0] = r[2]; Bh[2 * g + 1][1] = r[3];
            }
            #pragma unroll
            for (int mf = 0; mf < 4; mf++)
                #pragma unroll
                for (int nf = 0; nf < 4; nf++)
                    mma_f16(acc[mf][nf], Af[mf], Bh[nf]);
        }
    }

    // ---- epilogue ----
    const int r0 = mblk * 128 + wm * 64 + (lane >> 2);
    const int c0 = nblk * 128 + wn * 32 + (lane & 3) * 2;
    #pragma unroll
    for (int mf = 0; mf < 4; mf++) {
        #pragma unroll
        for (int nf = 0; nf < 4; nf++) {
            const int n = c0 + nf * 8;
            const int m = r0 + mf * 16;
            float v0 = acc[mf][nf][0], v1 = acc[mf][nf][1];
            float v2 = acc[mf][nf][2], v3 = acc[mf][nf][3];
            if (mode == 0) {
                *(uint32_t*)(Ch + (size_t)m * CS + n)       = h2pack(v0 * QSCALE, v1 * QSCALE);
                *(uint32_t*)(Ch + (size_t)(m + 8) * CS + n) = h2pack(v2 * QSCALE, v3 * QSCALE);
            } else if (mode == 4) {
                *(uint32_t*)(Ch + (size_t)m * CS + n)       = h2pack(v0, v1);
                *(uint32_t*)(Ch + (size_t)(m + 8) * CS + n) = h2pack(v2, v3);
            } else if (mode == 2) {
                const float b0 = __ldg(bias + n), b1 = __ldg(bias + n + 1);
                v0 = 1.f / (1.f + __expf(-(v0 + b0)));
                v1 = 1.f / (1.f + __expf(-(v1 + b1)));
                v2 = 1.f / (1.f + __expf(-(v2 + b0)));
                v3 = 1.f / (1.f + __expf(-(v3 + b1)));
                *(uint32_t*)(Ch + (size_t)m * CS + n)       = h2pack(v0, v1);
                *(uint32_t*)(Ch + (size_t)(m + 8) * CS + n) = h2pack(v2, v3);
            } else {
                const float b0 = __ldg(bias + n), b1 = __ldg(bias + n + 1);
                *(float2*)(Cf + (size_t)m * CS + n)       = make_float2(v0 + b0, v1 + b1);
                *(float2*)(Cf + (size_t)(m + 8) * CS + n) = make_float2(v2 + b0, v3 + b1);
            }
        }
    }
}

// Grid (8, 512): x packs (w, nblk) so the 8 CTAs sharing an A tile (same mblk)
// are adjacent -> concurrent -> A read ~once from DRAM/L2 per wave.
__global__ void __launch_bounds__(256, 2) gemm_proj(const float* __restrict__ bg)
{
    const int w = blockIdx.x >> 1;
    const int nblk = blockIdx.x & 1;
    const int mblk = blockIdx.y;
    const __half* bh = g_wt + (size_t)w * 65536;
    if (w == 0)
        gemm_body(g_x, bh, nullptr, nullptr, g_q, 0, mblk, nblk);
    else if (w == 1)
        gemm_body(g_x, bh, nullptr, nullptr, g_k, 4, mblk, nblk);
    else if (w == 2)
        gemm_body(g_x, bh, nullptr, nullptr, g_v, 4, mblk, nblk);
    else
        gemm_body(g_x, bh, bg, nullptr, g_g, 2, mblk, nblk);
}

__global__ void __launch_bounds__(256, 2) gemm_outp(const float* __restrict__ bo,
                                                    float* __restrict__ out)
{
    // Grid (2, 512): nblk fastest so the 2 CTAs sharing an A tile are adjacent.
    gemm_body(g_gv, g_wt + (size_t)4 * 65536, bo, out, nullptr, 3,
              blockIdx.y, blockIdx.x);
}

// ---------------------------------------------------------------------------
// Kernel 3: tensor-core column attention (R13/R15 proven config).
// Grid (i, h). Block = one (i, h). 256 thr = 8 warps, 32 queries/warp,
// 2 CTAs/SM. lsum via ones-MMA. Stage = K, V @ 64 rows x 80B.
// ---------------------------------------------------------------------------
#define AQ_SZ   20480u
#define AST_OFF 20480u
#define AST_SZ  10240u
#define ATTN_SMEM (20480 + 3 * 10240)

__device__ __forceinline__ void load_kv_stage(uint32_t stbase, int i, int h, int t0, int tid)
{
    #pragma unroll
    for (int j = 0; j < 2; j++) {
        const int u = tid + 256 * j;
        const int arr = u >> 8;
        const int rem = u & 255;
        const int row = rem >> 2;
        const int c = rem & 3;
        const __half* base = (arr == 0) ? g_k : g_v;
        const __half* src = base + ((size_t)(t0 + row) * I_DIM + i) * CS + h * HD + c * 8;
        cpa16(stbase + (uint32_t)(arr * 5120 + row * 80 + c * 16), src);
    }
}

__global__ void __launch_bounds__(256, 2) attn_kernel()
{
    extern __shared__ unsigned char sm[];
    const uint32_t sb = smem_u32(sm);
    const int i = blockIdx.x;
    const int h = blockIdx.y;
    const int tid = threadIdx.x;
    const int lane = tid & 31;
    const int wq = tid >> 5;

    #pragma unroll
    for (int j = 0; j < 4; j++) {
        const int u = tid + 256 * j;
        const int row = u >> 2, c = u & 3;
        cpa16(sb + (uint32_t)(row * 80 + c * 16),
              g_q + ((size_t)row * I_DIM + i) * CS + h * HD + c * 8);
    }
    cpa_commit();
    load_kv_stage(sb + AST_OFF, i, h, 0, tid);
    cpa_commit();
    load_kv_stage(sb + AST_OFF + AST_SZ, i, h, 64, tid);
    cpa_commit();

    cpa_wait<2>();
    __syncthreads();

    uint32_t qf[2][2][4];
    #pragma unroll
    for (int mf = 0; mf < 2; mf++) {
        const uint32_t qrow = (uint32_t)((wq * 32 + mf * 16 + (lane & 15)) * 80
                                         + (lane >> 4) * 16);
        ldsm4(qf[mf][0], sb + qrow);
        ldsm4(qf[mf][1], sb + qrow + 32u);
    }

    float o[2][4][4];
    #pragma unroll
    for (int mf = 0; mf < 2; mf++)
        #pragma unroll
        for (int nf = 0; nf < 4; nf++)
            #pragma unroll
            for (int q = 0; q < 4; q++) o[mf][nf][q] = 0.f;
    float lacc[2][4];
    #pragma unroll
    for (int mf = 0; mf < 2; mf++)
        #pragma unroll
        for (int q = 0; q < 4; q++) lacc[mf][q] = 0.f;

    const uint32_t ones[2] = {0x3C003C00u, 0x3C003C00u};

    const uint32_t kaddr = (uint32_t)((((lane >> 4) * 8) + (lane & 7)) * 80 + ((lane >> 3) & 1) * 16);
    const uint32_t vaddr = (uint32_t)(((((lane >> 3) & 1) * 8) + (lane & 7)) * 80 + (lane >> 4) * 16);

    for (int kt = 0; kt < 4; kt++) {
        if (kt < 3) cpa_wait<1>(); else cpa_wait<0>();
        __syncthreads();
        if (kt + 2 < 4) {
            load_kv_stage(sb + AST_OFF + (uint32_t)((kt + 2) % 3) * AST_SZ, i, h, (kt + 2) * 64, tid);
            cpa_commit();
        }
        const uint32_t st = sb + AST_OFF + (uint32_t)(kt % 3) * AST_SZ;

        #pragma unroll
        for (int ch = 0; ch < 4; ch++) {
            const uint32_t roff = (uint32_t)(ch * 16 * 80);

            float s[2][2][4];
            #pragma unroll
            for (int nt = 0; nt < 2; nt++)
                #pragma unroll
                for (int mf = 0; mf < 2; mf++)
                    #pragma unroll
                    for (int q = 0; q < 4; q++) s[nt][mf][q] = 0.f;

            #pragma unroll
            for (int ks = 0; ks < 2; ks++) {
                uint32_t bh[2][2], r[4];
                ldsm4(r, st + roff + kaddr + (uint32_t)(ks * 32));
                bh[0][0] = r[0]; bh[0][1] = r[1]; bh[1][0] = r[2]; bh[1][1] = r[3];
                #pragma unroll
                for (int nt = 0; nt < 2; nt++)
                    #pragma unroll
                    for (int mf = 0; mf < 2; mf++)
                        mma_f16(s[nt][mf], qf[mf][ks], bh[nt]);
            }

            uint32_t vhf[4][2];
            #pragma unroll
            for (int np2 = 0; np2 < 2; np2++) {
                uint32_t r[4];
                ldsm4t(r, st + 5120u + roff + vaddr + (uint32_t)(np2 * 32));
                vhf[2 * np2][0] = r[0]; vhf[2 * np2][1] = r[1];
                vhf[2 * np2 + 1][0] = r[2]; vhf[2 * np2 + 1][1] = r[3];
            }

            #pragma unroll
            for (int mf = 0; mf < 2; mf++) {
                float* sa = s[0][mf];
                float* sc = s[1][mf];
                sa[0] = ex2f(sa[0]); sa[1] = ex2f(sa[1]);
                sa[2] = ex2f(sa[2]); sa[3] = ex2f(sa[3]);
                sc[0] = ex2f(sc[0]); sc[1] = ex2f(sc[1]);
                sc[2] = ex2f(sc[2]); sc[3] = ex2f(sc[3]);
                uint32_t pA[4];
                pA[0] = h2pack(sa[0], sa[1]);
                pA[1] = h2pack(sa[2], sa[3]);
                pA[2] = h2pack(sc[0], sc[1]);
                pA[3] = h2pack(sc[2], sc[3]);
                mma_f16(lacc[mf], pA, ones);
                #pragma unroll
                for (int nf = 0; nf < 4; nf++)
                    mma_f16(o[mf][nf], pA, vhf[nf]);
            }
        }
    }

    #pragma unroll
    for (int mf = 0; mf < 2; mf++) {
        const float inv0 = 1.f / lacc[mf][0];
        const float inv1 = 1.f / lacc[mf][2];

        const int row = wq * 32 + mf * 16 + (lane >> 2);
        const size_t M0 = ((size_t)row * I_DIM + i) * CS + h * HD;
        const size_t M1 = ((size_t)(row + 8) * I_DIM + i) * CS + h * HD;
        #pragma unroll
        for (int nf = 0; nf < 4; nf++) {
            const int col = nf * 8 + (lane & 3) * 2;
            const float2 g0 = __half22float2(*(const __half2*)(g_g + M0 + col));
            const float2 g1 = __half22float2(*(const __half2*)(g_g + M1 + col));
            *(uint32_t*)(g_gv + M0 + col) =
                h2pack(o[mf][nf][0] * inv0 * g0.x, o[mf][nf][1] * inv0 * g0.y);
            *(uint32_t*)(g_gv + M1 + col) =
                h2pack(o[mf][nf][2] * inv1 * g1.x, o[mf][nf][3] * inv1 * g1.y);
        }
    }
}

// ---------------------------------------------------------------------------
// Launch
// ---------------------------------------------------------------------------
extern "C" void kernel_launch(void* const* d_in, const int* in_sizes, int n_in,
                              void* d_out, int out_size)
{
    const float* msa   = (const float*)d_in[0];
    const float* gamma = (const float*)d_in[1];
    const float* beta  = (const float*)d_in[2];
    const float* Wq    = (const float*)d_in[3];
    const float* Wk    = (const float*)d_in[4];
    const float* Wv    = (const float*)d_in[5];
    const float* Wg    = (const float*)d_in[6];
    const float* bg    = (const float*)d_in[7];
    const float* Wo    = (const float*)d_in[8];
    const float* bo    = (const float*)d_in[9];
    float* out = (float*)d_out;

    cudaFuncSetAttribute(gemm_proj, cudaFuncAttributeMaxDynamicSharedMemorySize, GEMM_SMEM);
    cudaFuncSetAttribute(gemm_outp, cudaFuncAttributeMaxDynamicSharedMemorySize, GEMM_SMEM);
    cudaFuncSetAttribute(attn_kernel, cudaFuncAttributeMaxDynamicSharedMemorySize, ATTN_SMEM);

    prep_kernel<<<LN_BLOCKS + WP_BLOCKS, 256>>>(msa, gamma, beta, Wq, Wk, Wv, Wg, Wo);

    gemm_proj<<<dim3(8, MBLOCKS), 256, GEMM_SMEM>>>(bg);

    attn_kernel<<<dim3(I_DIM, NH), 256, ATTN_SMEM>>>();

    gemm_outp<<<dim3(2, MBLOCKS), 256, GEMM_SMEM>>>(bo, out);
}